// round 12
// baseline (speedup 1.0000x reference)
#include <cuda_runtime.h>
#include <cuda_fp16.h>
#include <math.h>
#include <stdint.h>

#define B_  8
#define S_  2048
#define H_  8
#define DK_ 64
#define HD_ 512   // H_*DK_
#define DM_ 512
#define NB  (S_ / 64)   // kv blocks

// Scratch (static device arrays; allocation APIs are forbidden)
__device__ __align__(128) __half g_q[(size_t)H_ * B_ * S_ * DK_];
__device__ __align__(128) __half g_k[(size_t)H_ * B_ * S_ * DK_];
__device__ __align__(128) __half g_vT[(size_t)H_ * B_ * DK_ * S_];  // [h,b][d][s]
__device__ __align__(128) __half g_y[(size_t)B_ * S_ * HD_];        // attn out, fp16
__device__ __align__(128) __half g_WqT[HD_ * DK_];                  // [N=512][K=64]
__device__ __align__(128) __half g_WoT[DM_ * HD_];                  // [N=512][K=512]
__device__ uint32_t g_mb[(size_t)B_ * S_ * (S_ / 32)];   // bit-packed mask (4MB)

// ---------------------------------------------------------------------------
// helpers
// ---------------------------------------------------------------------------
// fp16: D += A(m16k16, row) * B(k16n8, col), fp32 accum
__device__ __forceinline__ void mma16(float* c, const uint32_t* a, const uint32_t* b) {
    asm volatile(
        "mma.sync.aligned.m16n8k16.row.col.f32.f16.f16.f32 "
        "{%0,%1,%2,%3}, {%4,%5,%6,%7}, {%8,%9}, {%0,%1,%2,%3};"
        : "+f"(c[0]), "+f"(c[1]), "+f"(c[2]), "+f"(c[3])
        : "r"(a[0]), "r"(a[1]), "r"(a[2]), "r"(a[3]), "r"(b[0]), "r"(b[1]));
}

__device__ __forceinline__ uint32_t smem_u32(const void* p) {
    uint32_t a;
    asm("{ .reg .u64 t; cvta.to.shared.u64 t, %1; cvt.u32.u64 %0, t; }"
        : "=r"(a) : "l"(p));
    return a;
}

__device__ __forceinline__ uint32_t packh2(float a, float b) {
    __half2 h = __floats2half2_rn(a, b);
    return *(uint32_t*)&h;
}

#define CP16(dst, src) \
    asm volatile("cp.async.cg.shared.global [%0], [%1], 16;" \
                 :: "r"(dst), "l"(src) : "memory")
#define CP_COMMIT() asm volatile("cp.async.commit_group;" ::: "memory")
#define CP_WAIT(n)  asm volatile("cp.async.wait_group %0;" :: "n"(n) : "memory")

// ---------------------------------------------------------------------------
// Pre-passes
// ---------------------------------------------------------------------------
__global__ void pack_mask(const float* __restrict__ mask, uint32_t* __restrict__ mb)
{
    const size_t i = (size_t)blockIdx.x * 256 + threadIdx.x;
    const uint32_t bits = __ballot_sync(0xffffffffu, mask[i] == 1.0f);
    if ((threadIdx.x & 31) == 0) mb[i >> 5] = bits;
}

// coalesced transpose+convert: WT[n][k] = (half)W[k][n]
__global__ void wT_kernel(const float* __restrict__ W, __half* __restrict__ WT,
                          int K, int N)
{
    __shared__ float tile[32][33];
    const int n0 = blockIdx.x * 32, k0 = blockIdx.y * 32;
    const int tx = threadIdx.x & 31, ty = threadIdx.x >> 5;   // 256 threads
#pragma unroll
    for (int i = 0; i < 32; i += 8)
        tile[ty + i][tx] = W[(size_t)(k0 + ty + i) * N + n0 + tx];
    __syncthreads();
#pragma unroll
    for (int i = 0; i < 32; i += 8)
        WT[(size_t)(n0 + ty + i) * K + k0 + tx] = __float2half_rn(tile[tx][ty + i]);
}

// ---------------------------------------------------------------------------
// smem layout constants (stride 72 halves = 36 words, ==4 mod 32: conflict-free)
// ---------------------------------------------------------------------------
#define KW 36
#define TILE_W (64 * KW)              // 2304 words per 64-row tile

// stage a 64-row x 64-half tile via cp.async (fp16 source)
__device__ __forceinline__ void stage_h(uint32_t dst, const __half* __restrict__ src,
                                        int stride_h, int t)
{
#pragma unroll
    for (int i = 0; i < 4; i++) {
        const int chunk = t + i * 128;          // 0..511 (128 threads)
        const int row = chunk >> 3, col = chunk & 7;
        CP16(dst + row * 144 + col * 16, src + (size_t)row * stride_h + col * 8);
    }
}

// ---------------------------------------------------------------------------
// Fused q/k/v projection, fp16 mma, fp32 input converted in staging.
//   z=0: q -> g_q  (scale log2e/8, half2 scatter [h,b,s,d])
//   z=1: k -> g_k  (half2 scatter)
//   z=2: v -> g_vT (half scatter transposed [h,b,d,s])
// ---------------------------------------------------------------------------
#define PROJ_SMEM (2 * TILE_W * 4)    // 18432 bytes

__global__ void __launch_bounds__(128) proj_h(
    const float* __restrict__ q, const float* __restrict__ k,
    const float* __restrict__ v, const __half* __restrict__ WqT,
    const float* __restrict__ bias,
    __half* __restrict__ gq, __half* __restrict__ gk, __half* __restrict__ gvT)
{
    extern __shared__ uint32_t smu[];
    const uint32_t smb = smem_u32(smu);

    const int z = blockIdx.z;
    const float* A = (z == 0) ? q : (z == 1) ? k : v;
    // q gets 1/sqrt(DK) * log2(e) so attention can use exp2 directly
    const float scale = (z == 0) ? 0.18033688011112042f : 1.0f;

    const int t = threadIdx.x;
    const int w = t >> 5, lane = t & 31;
    const int rr = lane >> 2, cc = lane & 3;
    const int row0 = blockIdx.y * 64, col0 = blockIdx.x * 64;

    // W tile via cp.async (fp16), A tile via LDG+cvt+STS (fp32 source)
    stage_h(smb + TILE_W * 4, WqT + (size_t)col0 * DK_, DK_, t);
    CP_COMMIT();
    {
        const float* Asrc = A + (size_t)row0 * DK_;
#pragma unroll
        for (int i = 0; i < 4; i++) {
            const int chunk = t + i * 128;
            const int row = chunk >> 3, col = chunk & 7;
            const float4 f0 = *(const float4*)&Asrc[row * DK_ + col * 8];
            const float4 f1 = *(const float4*)&Asrc[row * DK_ + col * 8 + 4];
            uint4 u = make_uint4(packh2(f0.x, f0.y), packh2(f0.z, f0.w),
                                 packh2(f1.x, f1.y), packh2(f1.z, f1.w));
            *(uint4*)((char*)smu + row * 144 + col * 16) = u;
        }
    }
    CP_WAIT(0);
    __syncthreads();

    float o[8][4];
#pragma unroll
    for (int i = 0; i < 8; i++)
#pragma unroll
        for (int j = 0; j < 4; j++) o[i][j] = 0.0f;

    const uint32_t* Aw = smu;
    const uint32_t* Ww = smu + TILE_W;
#pragma unroll
    for (int ks = 0; ks < 4; ks++) {
        uint32_t af[4];
        const int ar = (w * 16 + rr) * KW + ks * 8 + cc;
        af[0] = Aw[ar];
        af[1] = Aw[ar + 8 * KW];
        af[2] = Aw[ar + 4];
        af[3] = Aw[ar + 8 * KW + 4];
#pragma unroll
        for (int nt = 0; nt < 8; nt++) {
            uint32_t bv[2];
            bv[0] = Ww[(nt * 8 + rr) * KW + ks * 8 + cc];
            bv[1] = Ww[(nt * 8 + rr) * KW + ks * 8 + cc + 4];
            mma16(o[nt], af, bv);
        }
    }

#pragma unroll
    for (int nt = 0; nt < 8; nt++) {
#pragma unroll
        for (int half = 0; half < 2; half++) {
            const int row = row0 + w * 16 + rr + half * 8;
            const int col = col0 + nt * 8 + 2 * cc;
            const float v0 = (o[nt][half * 2 + 0] + bias[col]) * scale;
            const float v1 = (o[nt][half * 2 + 1] + bias[col + 1]) * scale;
            const int bb = row >> 11;            // /S_
            const int s  = row & (S_ - 1);
            const int hh = col >> 6;             // /DK_
            const int d  = col & (DK_ - 1);
            if (z < 2) {
                __half* C = (z == 0) ? gq : gk;
                __half2 hv = __floats2half2_rn(v0, v1);
                *(__half2*)&C[((size_t)(hh * B_ + bb) * S_ + s) * DK_ + d] = hv;
            } else {
                __half* dst = &gvT[((size_t)(hh * B_ + bb) * DK_ + d) * S_ + s];
                dst[0]  = __float2half_rn(v0);
                dst[S_] = __float2half_rn(v1);
            }
        }
    }
}

// ---------------------------------------------------------------------------
// Output GEMM, fp16 in / fp32 out: 128x128 CTA tile, 256 threads, 8 warps
// (2m x 4n), K=512 double-buffered. Warp tile 64x32.
// ---------------------------------------------------------------------------
#define OT_W (128 * KW)               // words per 128-row tile: 4608
#define GOUT_SMEM (4 * OT_W * 4)      // 73728 bytes

__device__ __forceinline__ void stage_h256(uint32_t dst, const __half* __restrict__ src,
                                           int stride_h, int t)
{
#pragma unroll
    for (int i = 0; i < 4; i++) {
        const int chunk = t + i * 256;          // 0..1023 (256 threads, 128 rows)
        const int row = chunk >> 3, col = chunk & 7;
        CP16(dst + row * 144 + col * 16, src + (size_t)row * stride_h + col * 8);
    }
}

__global__ void __launch_bounds__(256) gemm_out_h(
    const __half* __restrict__ A, const __half* __restrict__ WT,
    const float* __restrict__ bias, float* __restrict__ C)
{
    extern __shared__ uint32_t smu[];
    const uint32_t smb = smem_u32(smu);

    const int t = threadIdx.x;
    const int w = t >> 5, lane = t & 31;
    const int wm = w >> 2, wn = w & 3;          // warp grid 2m x 4n
    const int rr = lane >> 2, cc = lane & 3;
    const int row0 = blockIdx.y * 128, col0 = blockIdx.x * 128;
    const int K = HD_, N = DM_;

    float o[4][4][4];                            // [mf][nt][frag]
#pragma unroll
    for (int i = 0; i < 4; i++)
#pragma unroll
        for (int j = 0; j < 4; j++)
#pragma unroll
            for (int l = 0; l < 4; l++) o[i][j][l] = 0.0f;

    stage_h256(smb, A + (size_t)row0 * K, K, t);
    stage_h256(smb + OT_W * 4, WT + (size_t)col0 * K, K, t);
    CP_COMMIT();

    for (int kb = 0; kb < K / 64; kb++) {
        const int buf = kb & 1;
        if (kb + 1 < K / 64) {
            const uint32_t nb = smb + (buf ^ 1) * 2 * OT_W * 4;
            stage_h256(nb, A + (size_t)row0 * K + (kb + 1) * 64, K, t);
            stage_h256(nb + OT_W * 4, WT + (size_t)col0 * K + (kb + 1) * 64, K, t);
            CP_COMMIT();
            CP_WAIT(1);
        } else {
            CP_WAIT(0);
        }
        __syncthreads();

        const uint32_t* Aw = smu + buf * 2 * OT_W;
        const uint32_t* Bw = Aw + OT_W;
#pragma unroll
        for (int ks = 0; ks < 4; ks++) {
            uint32_t af[4][4];
#pragma unroll
            for (int mf = 0; mf < 4; mf++) {
                const int ar = (wm * 64 + mf * 16 + rr) * KW + ks * 8 + cc;
                af[mf][0] = Aw[ar];
                af[mf][1] = Aw[ar + 8 * KW];
                af[mf][2] = Aw[ar + 4];
                af[mf][3] = Aw[ar + 8 * KW + 4];
            }
#pragma unroll
            for (int nt = 0; nt < 4; nt++) {
                uint32_t bv[2];
                const int br = (wn * 32 + nt * 8 + rr) * KW + ks * 8 + cc;
                bv[0] = Bw[br];
                bv[1] = Bw[br + 4];
#pragma unroll
                for (int mf = 0; mf < 4; mf++)
                    mma16(o[mf][nt], af[mf], bv);
            }
        }
        __syncthreads();
    }

#pragma unroll
    for (int mf = 0; mf < 4; mf++)
#pragma unroll
        for (int nt = 0; nt < 4; nt++)
#pragma unroll
            for (int half = 0; half < 2; half++) {
                const int row = row0 + wm * 64 + mf * 16 + rr + half * 8;
                const int col = col0 + wn * 32 + nt * 8 + 2 * cc;
                const float v0 = o[mf][nt][half * 2 + 0] + bias[col];
                const float v1 = o[mf][nt][half * 2 + 1] + bias[col + 1];
                *(float2*)&C[(size_t)row * N + col] = make_float2(v0, v1);
            }
}

// ---------------------------------------------------------------------------
// Flash attention, fp16 mma m16n8k16, no-max softmax via exp2 (log2e folded
// into the Q projection scale), P in registers (S C-frag == PV A-frag).
// ---------------------------------------------------------------------------
#define KOFF(buf) ((buf) * 2 * TILE_W)
#define VOFF(buf) (KOFF(buf) + TILE_W)
#define ATTN_SMEM (4 * TILE_W * 4)    // 36864 bytes

__device__ __forceinline__ void stage_kv(uint32_t smb, int buf,
                                         const __half* __restrict__ Kg,
                                         const __half* __restrict__ VTg,
                                         int k0, int t)
{
    const uint32_t kb = smb + KOFF(buf) * 4;
    const uint32_t vb = smb + VOFF(buf) * 4;
#pragma unroll
    for (int i = 0; i < 4; i++) {
        const int chunk = t + i * 128;
        const int row = chunk >> 3, col = chunk & 7;
        CP16(kb + row * 144 + col * 16, Kg + (size_t)(k0 + row) * DK_ + col * 8);
        CP16(vb + row * 144 + col * 16, VTg + (size_t)row * S_ + k0 + col * 8);
    }
}

__global__ void __launch_bounds__(128, 2) attn_mma(const uint32_t* __restrict__ mbits,
                                                   __half* __restrict__ Y)
{
    extern __shared__ uint32_t smu[];
    const uint32_t smb = smem_u32(smu);

    const int h = blockIdx.x, qb = blockIdx.y, b = blockIdx.z;
    const int t = threadIdx.x;
    const int w = t >> 5, lane = t & 31;
    const int rr = lane >> 2, cc = lane & 3;

    const size_t base = (size_t)(h * B_ + b) * S_ * DK_;
    const __half* Qg  = g_q + base + (size_t)qb * 128 * DK_;
    const __half* Kg  = g_k + base;
    const __half* VTg = g_vT + base;

    const uint32_t* Qw = (const uint32_t*)Qg;
    uint32_t qf[4][2][4];
#pragma unroll
    for (int mf = 0; mf < 2; mf++) {
        const int q0 = w * 32 + mf * 16 + rr;
#pragma unroll
        for (int ks = 0; ks < 4; ks++) {
            qf[ks][mf][0] = Qw[q0 * 32 + ks * 8 + cc];
            qf[ks][mf][1] = Qw[(q0 + 8) * 32 + ks * 8 + cc];
            qf[ks][mf][2] = Qw[q0 * 32 + ks * 8 + cc + 4];
            qf[ks][mf][3] = Qw[(q0 + 8) * 32 + ks * 8 + cc + 4];
        }
    }

    float o0[8][4], o1[8][4];
#pragma unroll
    for (int i = 0; i < 8; i++)
#pragma unroll
        for (int j = 0; j < 4; j++) { o0[i][j] = 0.0f; o1[i][j] = 0.0f; }

    float l_[4] = {0.0f, 0.0f, 0.0f, 0.0f};
    const size_t mrow = ((size_t)b * S_ + (size_t)qb * 128 + w * 32 + rr) * (S_ / 32);

    stage_kv(smb, 0, Kg, VTg, 0, t);
    CP_COMMIT();

    for (int kb = 0; kb < NB; kb++) {
        const int buf = kb & 1;

        const uint2 M0 = *(const uint2*)&mbits[mrow + 0 * 8 * (S_ / 32) + kb * 2];
        const uint2 M1 = *(const uint2*)&mbits[mrow + 1 * 8 * (S_ / 32) + kb * 2];
        const uint2 M2 = *(const uint2*)&mbits[mrow + 2 * 8 * (S_ / 32) + kb * 2];
        const uint2 M3 = *(const uint2*)&mbits[mrow + 3 * 8 * (S_ / 32) + kb * 2];

        if (kb + 1 < NB) {
            stage_kv(smb, buf ^ 1, Kg, VTg, (kb + 1) * 64, t);
            CP_COMMIT();
            CP_WAIT(1);
        } else {
            CP_WAIT(0);
        }
        __syncthreads();

        const uint32_t* Ks = smu + KOFF(buf);
        const uint32_t* Vs = smu + VOFF(buf);

        uint32_t pf0[4][4], pf1[4][4];

#pragma unroll
        for (int half = 0; half < 2; half++) {
            float s0[4][4], s1[4][4];
#pragma unroll
            for (int i = 0; i < 4; i++)
#pragma unroll
                for (int j = 0; j < 4; j++) { s0[i][j] = 0.0f; s1[i][j] = 0.0f; }

#pragma unroll
            for (int ks = 0; ks < 4; ks++) {
#pragma unroll
                for (int nt = 0; nt < 4; nt++) {
                    const int n8 = (half * 4 + nt) * 8;
                    uint32_t bv[2];
                    bv[0] = Ks[(n8 + rr) * KW + ks * 8 + cc];
                    bv[1] = Ks[(n8 + rr) * KW + ks * 8 + cc + 4];
                    mma16(s0[nt], qf[ks][0], bv);
                    mma16(s1[nt], qf[ks][1], bv);
                }
            }

            // 2^s (log2e pre-folded) + mask-zero + accumulate l + pack A-frags
#pragma unroll
            for (int nt = 0; nt < 4; nt++) {
                const int ntg = half * 4 + nt;
                const int sh = (ntg * 8 + 2 * cc) & 31;
                const uint32_t w0 = (ntg < 4) ? M0.x : M0.y;
                const uint32_t w1 = (ntg < 4) ? M1.x : M1.y;
                const uint32_t w2 = (ntg < 4) ? M2.x : M2.y;
                const uint32_t w3 = (ntg < 4) ? M3.x : M3.y;
                float e00 = ((w0 >> sh) & 1u)       ? 0.0f : exp2f(s0[nt][0]);
                float e01 = ((w0 >> (sh + 1)) & 1u) ? 0.0f : exp2f(s0[nt][1]);
                float e10 = ((w1 >> sh) & 1u)       ? 0.0f : exp2f(s0[nt][2]);
                float e11 = ((w1 >> (sh + 1)) & 1u) ? 0.0f : exp2f(s0[nt][3]);
                float e20 = ((w2 >> sh) & 1u)       ? 0.0f : exp2f(s1[nt][0]);
                float e21 = ((w2 >> (sh + 1)) & 1u) ? 0.0f : exp2f(s1[nt][1]);
                float e30 = ((w3 >> sh) & 1u)       ? 0.0f : exp2f(s1[nt][2]);
                float e31 = ((w3 >> (sh + 1)) & 1u) ? 0.0f : exp2f(s1[nt][3]);
                l_[0] += e00 + e01; l_[1] += e10 + e11;
                l_[2] += e20 + e21; l_[3] += e30 + e31;
                const int ks = ntg >> 1, hi = (ntg & 1) << 1;
                pf0[ks][hi + 0] = packh2(e00, e01);
                pf0[ks][hi + 1] = packh2(e10, e11);
                pf1[ks][hi + 0] = packh2(e20, e21);
                pf1[ks][hi + 1] = packh2(e30, e31);
            }
        }

#pragma unroll
        for (int ks = 0; ks < 4; ks++) {
#pragma unroll
            for (int nt = 0; nt < 8; nt++) {
                uint32_t bv[2];
                bv[0] = Vs[(nt * 8 + rr) * KW + ks * 8 + cc];
                bv[1] = Vs[(nt * 8 + rr) * KW + ks * 8 + cc + 4];
                mma16(o0[nt], pf0[ks], bv);
                mma16(o1[nt], pf1[ks], bv);
            }
        }
        __syncthreads();
    }

#pragma unroll
    for (int i = 0; i < 4; i++) {
        l_[i] += __shfl_xor_sync(0xffffffffu, l_[i], 1);
        l_[i] += __shfl_xor_sync(0xffffffffu, l_[i], 2);
    }
    const float il0 = 1.0f / l_[0], il1 = 1.0f / l_[1];
    const float il2 = 1.0f / l_[2], il3 = 1.0f / l_[3];

    const size_t yr0 = ((size_t)b * S_ + (size_t)qb * 128 + w * 32 + rr) * HD_ + h * DK_;
#pragma unroll
    for (int nt = 0; nt < 8; nt++) {
        const int col = nt * 8 + 2 * cc;
        *(__half2*)&Y[yr0 + col]                    = __floats2half2_rn(o0[nt][0] * il0, o0[nt][1] * il0);
        *(__half2*)&Y[yr0 + (size_t)8 * HD_ + col]  = __floats2half2_rn(o0[nt][2] * il1, o0[nt][3] * il1);
        *(__half2*)&Y[yr0 + (size_t)16 * HD_ + col] = __floats2half2_rn(o1[nt][0] * il2, o1[nt][1] * il2);
        *(__half2*)&Y[yr0 + (size_t)24 * HD_ + col] = __floats2half2_rn(o1[nt][2] * il3, o1[nt][3] * il3);
    }
}

// ---------------------------------------------------------------------------
extern "C" void kernel_launch(void* const* d_in, const int* in_sizes, int n_in,
                              void* d_out, int out_size)
{
    const float* q    = (const float*)d_in[0];
    const float* k    = (const float*)d_in[1];
    const float* v    = (const float*)d_in[2];
    const float* mask = (const float*)d_in[3];
    const float* Wq   = (const float*)d_in[4];
    const float* bq   = (const float*)d_in[5];
    const float* Wo   = (const float*)d_in[6];
    const float* bo   = (const float*)d_in[7];
    float* out = (float*)d_out;

    __half *gq, *gk, *gvT, *gy, *gWqT, *gWoT;
    uint32_t* gmb;
    cudaGetSymbolAddress((void**)&gq, g_q);
    cudaGetSymbolAddress((void**)&gk, g_k);
    cudaGetSymbolAddress((void**)&gvT, g_vT);
    cudaGetSymbolAddress((void**)&gy, g_y);
    cudaGetSymbolAddress((void**)&gWqT, g_WqT);
    cudaGetSymbolAddress((void**)&gWoT, g_WoT);
    cudaGetSymbolAddress((void**)&gmb, g_mb);

    cudaFuncSetAttribute(gemm_out_h, cudaFuncAttributeMaxDynamicSharedMemorySize,
                         GOUT_SMEM);

    const int Mrows = B_ * S_;   // 16384
    dim3 blk(128);

    // pre-passes
    pack_mask<<<(int)(((size_t)B_ * S_ * S_) / 256), 256>>>(mask, gmb);
    wT_kernel<<<dim3(HD_ / 32, DK_ / 32), 256>>>(Wq, gWqT, DK_, HD_);
    wT_kernel<<<dim3(DM_ / 32, HD_ / 32), 256>>>(Wo, gWoT, HD_, DM_);

    // fused projections (reference bug: Wq/bq for q, k AND v);
    // q epilogue scale = log2(e)/sqrt(DK) so attention uses exp2 directly
    dim3 gproj(HD_ / 64, Mrows / 64, 3);
    proj_h<<<gproj, blk, PROJ_SMEM>>>(q, k, v, gWqT, bq, gq, gk, gvT);

    // flash attention (fp16 mma): grid.x = heads so heads share mask bits in L2
    dim3 gattn(H_, S_ / 128, B_);
    attn_mma<<<gattn, blk, ATTN_SMEM>>>(gmb, gy);

    // output projection (fp16 in, fp32 out), 128x128 tiles
    dim3 gout(DM_ / 128, Mrows / 128);
    gemm_out_h<<<gout, 256, GOUT_SMEM>>>(gy, gWoT, bo, out);
}

// round 13
// speedup vs baseline: 1.2208x; 1.2208x over previous
#include <cuda_runtime.h>
#include <cuda_fp16.h>
#include <math.h>
#include <stdint.h>

#define B_  8
#define S_  2048
#define H_  8
#define DK_ 64
#define HD_ 512   // H_*DK_
#define DM_ 512
#define NB  (S_ / 64)   // kv blocks

// Scratch (static device arrays; allocation APIs are forbidden)
__device__ __align__(128) __half g_q[(size_t)H_ * B_ * S_ * DK_];
__device__ __align__(128) __half g_k[(size_t)H_ * B_ * S_ * DK_];
__device__ __align__(128) __half g_vT[(size_t)H_ * B_ * DK_ * S_];  // [h,b][d][s]
__device__ __align__(128) __half g_y[(size_t)B_ * S_ * HD_];        // attn out, fp16
__device__ __align__(128) __half g_WqT[HD_ * DK_];                  // [N=512][K=64]
__device__ __align__(128) __half g_WoT[DM_ * HD_];                  // [N=512][K=512]
__device__ uint32_t g_mb[(size_t)B_ * S_ * (S_ / 32)];   // bit-packed mask (4MB)

// ---------------------------------------------------------------------------
// helpers
// ---------------------------------------------------------------------------
// fp16: D += A(m16k16, row) * B(k16n8, col), fp32 accum
__device__ __forceinline__ void mma16(float* c, const uint32_t* a, const uint32_t* b) {
    asm volatile(
        "mma.sync.aligned.m16n8k16.row.col.f32.f16.f16.f32 "
        "{%0,%1,%2,%3}, {%4,%5,%6,%7}, {%8,%9}, {%0,%1,%2,%3};"
        : "+f"(c[0]), "+f"(c[1]), "+f"(c[2]), "+f"(c[3])
        : "r"(a[0]), "r"(a[1]), "r"(a[2]), "r"(a[3]), "r"(b[0]), "r"(b[1]));
}

// hardware MUFU.EX2 — 2^x (log2e is pre-folded into the Q scale)
__device__ __forceinline__ float ex2(float x) {
    float r;
    asm("ex2.approx.ftz.f32 %0, %1;" : "=f"(r) : "f"(x));
    return r;
}

__device__ __forceinline__ uint32_t smem_u32(const void* p) {
    uint32_t a;
    asm("{ .reg .u64 t; cvta.to.shared.u64 t, %1; cvt.u32.u64 %0, t; }"
        : "=r"(a) : "l"(p));
    return a;
}

__device__ __forceinline__ uint32_t packh2(float a, float b) {
    __half2 h = __floats2half2_rn(a, b);
    return *(uint32_t*)&h;
}

#define CP16(dst, src) \
    asm volatile("cp.async.cg.shared.global [%0], [%1], 16;" \
                 :: "r"(dst), "l"(src) : "memory")
#define CP_COMMIT() asm volatile("cp.async.commit_group;" ::: "memory")
#define CP_WAIT(n)  asm volatile("cp.async.wait_group %0;" :: "n"(n) : "memory")

// ---------------------------------------------------------------------------
// Pre-passes
// ---------------------------------------------------------------------------
__global__ void pack_mask(const float* __restrict__ mask, uint32_t* __restrict__ mb)
{
    const size_t i = (size_t)blockIdx.x * 256 + threadIdx.x;
    const uint32_t bits = __ballot_sync(0xffffffffu, mask[i] == 1.0f);
    if ((threadIdx.x & 31) == 0) mb[i >> 5] = bits;
}

// coalesced transpose+convert: WT[n][k] = (half)W[k][n]
__global__ void wT_kernel(const float* __restrict__ W, __half* __restrict__ WT,
                          int K, int N)
{
    __shared__ float tile[32][33];
    const int n0 = blockIdx.x * 32, k0 = blockIdx.y * 32;
    const int tx = threadIdx.x & 31, ty = threadIdx.x >> 5;   // 256 threads
#pragma unroll
    for (int i = 0; i < 32; i += 8)
        tile[ty + i][tx] = W[(size_t)(k0 + ty + i) * N + n0 + tx];
    __syncthreads();
#pragma unroll
    for (int i = 0; i < 32; i += 8)
        WT[(size_t)(n0 + ty + i) * K + k0 + tx] = __float2half_rn(tile[tx][ty + i]);
}

// ---------------------------------------------------------------------------
// smem layout constants (stride 72 halves = 36 words, ==4 mod 32: conflict-free)
// ---------------------------------------------------------------------------
#define KW 36
#define TILE_W (64 * KW)              // 2304 words per 64-row tile

// stage a 64-row x 64-half tile via cp.async (fp16 source)
__device__ __forceinline__ void stage_h(uint32_t dst, const __half* __restrict__ src,
                                        int stride_h, int t)
{
#pragma unroll
    for (int i = 0; i < 4; i++) {
        const int chunk = t + i * 128;          // 0..511 (128 threads)
        const int row = chunk >> 3, col = chunk & 7;
        CP16(dst + row * 144 + col * 16, src + (size_t)row * stride_h + col * 8);
    }
}

// ---------------------------------------------------------------------------
// Fused q/k/v projection, fp16 mma, fp32 input converted in staging.
//   z=0: q -> g_q  (scale log2e/8, half2 scatter [h,b,s,d])
//   z=1: k -> g_k  (half2 scatter)
//   z=2: v -> g_vT (smem transpose, then coalesced 16B rows [h,b,d,s])
// ---------------------------------------------------------------------------
#define PROJ_SMEM (2 * TILE_W * 4)    // 18432 bytes

__global__ void __launch_bounds__(128) proj_h(
    const float* __restrict__ q, const float* __restrict__ k,
    const float* __restrict__ v, const __half* __restrict__ WqT,
    const float* __restrict__ bias,
    __half* __restrict__ gq, __half* __restrict__ gk, __half* __restrict__ gvT)
{
    extern __shared__ uint32_t smu[];
    const uint32_t smb = smem_u32(smu);

    const int z = blockIdx.z;
    const float* A = (z == 0) ? q : (z == 1) ? k : v;
    // q gets 1/sqrt(DK) * log2(e) so attention can use ex2 directly
    const float scale = (z == 0) ? 0.18033688011112042f : 1.0f;

    const int t = threadIdx.x;
    const int w = t >> 5, lane = t & 31;
    const int rr = lane >> 2, cc = lane & 3;
    const int row0 = blockIdx.y * 64, col0 = blockIdx.x * 64;

    // W tile via cp.async (fp16), A tile via LDG+cvt+STS (fp32 source)
    stage_h(smb + TILE_W * 4, WqT + (size_t)col0 * DK_, DK_, t);
    CP_COMMIT();
    {
        const float* Asrc = A + (size_t)row0 * DK_;
#pragma unroll
        for (int i = 0; i < 4; i++) {
            const int chunk = t + i * 128;
            const int row = chunk >> 3, col = chunk & 7;
            const float4 f0 = *(const float4*)&Asrc[row * DK_ + col * 8];
            const float4 f1 = *(const float4*)&Asrc[row * DK_ + col * 8 + 4];
            uint4 u = make_uint4(packh2(f0.x, f0.y), packh2(f0.z, f0.w),
                                 packh2(f1.x, f1.y), packh2(f1.z, f1.w));
            *(uint4*)((char*)smu + row * 144 + col * 16) = u;
        }
    }
    CP_WAIT(0);
    __syncthreads();

    float o[8][4];
#pragma unroll
    for (int i = 0; i < 8; i++)
#pragma unroll
        for (int j = 0; j < 4; j++) o[i][j] = 0.0f;

    const uint32_t* Aw = smu;
    const uint32_t* Ww = smu + TILE_W;
#pragma unroll
    for (int ks = 0; ks < 4; ks++) {
        uint32_t af[4];
        const int ar = (w * 16 + rr) * KW + ks * 8 + cc;
        af[0] = Aw[ar];
        af[1] = Aw[ar + 8 * KW];
        af[2] = Aw[ar + 4];
        af[3] = Aw[ar + 8 * KW + 4];
#pragma unroll
        for (int nt = 0; nt < 8; nt++) {
            uint32_t bv[2];
            bv[0] = Ww[(nt * 8 + rr) * KW + ks * 8 + cc];
            bv[1] = Ww[(nt * 8 + rr) * KW + ks * 8 + cc + 4];
            mma16(o[nt], af, bv);
        }
    }

    const int bb = row0 >> 11;          // /S_ (tile is within one b)
    const int s0 = row0 & (S_ - 1);
    const int hh = col0 >> 6;           // /DK_ (tile is exactly one head)

    if (z < 2) {
        __half* C = (z == 0) ? gq : gk;
#pragma unroll
        for (int nt = 0; nt < 8; nt++) {
#pragma unroll
            for (int half = 0; half < 2; half++) {
                const int row = row0 + w * 16 + rr + half * 8;
                const int col = col0 + nt * 8 + 2 * cc;
                const float v0 = (o[nt][half * 2 + 0] + bias[col]) * scale;
                const float v1 = (o[nt][half * 2 + 1] + bias[col + 1]) * scale;
                const int s = row & (S_ - 1);
                const int d = col & (DK_ - 1);
                __half2 hv = __floats2half2_rn(v0, v1);
                *(__half2*)&C[((size_t)(hh * B_ + bb) * S_ + s) * DK_ + d] = hv;
            }
        }
    } else {
        // transpose through smem, then coalesced 16B stores into g_vT[d][s]
        __syncthreads();                 // everyone done reading the mma tiles
        __half* Ts = (__half*)smu;       // [64 d][72 pad] halves = 9216 B
#pragma unroll
        for (int nt = 0; nt < 8; nt++) {
#pragma unroll
            for (int half = 0; half < 2; half++) {
                const int rloc = w * 16 + rr + half * 8;      // s within tile
                const int cloc = nt * 8 + 2 * cc;             // d within tile
                const int col = col0 + cloc;
                const float v0 = o[nt][half * 2 + 0] + bias[col];
                const float v1 = o[nt][half * 2 + 1] + bias[col + 1];
                Ts[cloc * 72 + rloc]       = __float2half_rn(v0);
                Ts[(cloc + 1) * 72 + rloc] = __float2half_rn(v1);
            }
        }
        __syncthreads();
        __half* dstb = gvT + ((size_t)(hh * B_ + bb) * DK_) * S_ + s0;
#pragma unroll
        for (int i = 0; i < 4; i++) {
            const int j = t + i * 128;               // 0..511
            const int d = j >> 3, sc = (j & 7) * 8;
            uint4 val = *(uint4*)&Ts[d * 72 + sc];
            *(uint4*)&dstb[(size_t)d * S_ + sc] = val;
        }
    }
}

// ---------------------------------------------------------------------------
// Output GEMM, fp16 in / fp32 out: 128x128 CTA tile, 256 threads, 8 warps
// (2m x 4n), K=512 double-buffered. Warp tile 64x32.
// ---------------------------------------------------------------------------
#define OT_W (128 * KW)               // words per 128-row tile: 4608
#define GOUT_SMEM (4 * OT_W * 4)      // 73728 bytes

__device__ __forceinline__ void stage_h256(uint32_t dst, const __half* __restrict__ src,
                                           int stride_h, int t)
{
#pragma unroll
    for (int i = 0; i < 4; i++) {
        const int chunk = t + i * 256;          // 0..1023 (256 threads, 128 rows)
        const int row = chunk >> 3, col = chunk & 7;
        CP16(dst + row * 144 + col * 16, src + (size_t)row * stride_h + col * 8);
    }
}

__global__ void __launch_bounds__(256) gemm_out_h(
    const __half* __restrict__ A, const __half* __restrict__ WT,
    const float* __restrict__ bias, float* __restrict__ C)
{
    extern __shared__ uint32_t smu[];
    const uint32_t smb = smem_u32(smu);

    const int t = threadIdx.x;
    const int w = t >> 5, lane = t & 31;
    const int wm = w >> 2, wn = w & 3;          // warp grid 2m x 4n
    const int rr = lane >> 2, cc = lane & 3;
    const int row0 = blockIdx.y * 128, col0 = blockIdx.x * 128;
    const int K = HD_, N = DM_;

    float o[4][4][4];                            // [mf][nt][frag]
#pragma unroll
    for (int i = 0; i < 4; i++)
#pragma unroll
        for (int j = 0; j < 4; j++)
#pragma unroll
            for (int l = 0; l < 4; l++) o[i][j][l] = 0.0f;

    stage_h256(smb, A + (size_t)row0 * K, K, t);
    stage_h256(smb + OT_W * 4, WT + (size_t)col0 * K, K, t);
    CP_COMMIT();

    for (int kb = 0; kb < K / 64; kb++) {
        const int buf = kb & 1;
        if (kb + 1 < K / 64) {
            const uint32_t nb = smb + (buf ^ 1) * 2 * OT_W * 4;
            stage_h256(nb, A + (size_t)row0 * K + (kb + 1) * 64, K, t);
            stage_h256(nb + OT_W * 4, WT + (size_t)col0 * K + (kb + 1) * 64, K, t);
            CP_COMMIT();
            CP_WAIT(1);
        } else {
            CP_WAIT(0);
        }
        __syncthreads();

        const uint32_t* Aw = smu + buf * 2 * OT_W;
        const uint32_t* Bw = Aw + OT_W;
#pragma unroll
        for (int ks = 0; ks < 4; ks++) {
            uint32_t af[4][4];
#pragma unroll
            for (int mf = 0; mf < 4; mf++) {
                const int ar = (wm * 64 + mf * 16 + rr) * KW + ks * 8 + cc;
                af[mf][0] = Aw[ar];
                af[mf][1] = Aw[ar + 8 * KW];
                af[mf][2] = Aw[ar + 4];
                af[mf][3] = Aw[ar + 8 * KW + 4];
            }
#pragma unroll
            for (int nt = 0; nt < 4; nt++) {
                uint32_t bv[2];
                const int br = (wn * 32 + nt * 8 + rr) * KW + ks * 8 + cc;
                bv[0] = Bw[br];
                bv[1] = Bw[br + 4];
#pragma unroll
                for (int mf = 0; mf < 4; mf++)
                    mma16(o[mf][nt], af[mf], bv);
            }
        }
        __syncthreads();
    }

#pragma unroll
    for (int mf = 0; mf < 4; mf++)
#pragma unroll
        for (int nt = 0; nt < 4; nt++)
#pragma unroll
            for (int half = 0; half < 2; half++) {
                const int row = row0 + wm * 64 + mf * 16 + rr + half * 8;
                const int col = col0 + wn * 32 + nt * 8 + 2 * cc;
                const float v0 = o[mf][nt][half * 2 + 0] + bias[col];
                const float v1 = o[mf][nt][half * 2 + 1] + bias[col + 1];
                *(float2*)&C[(size_t)row * N + col] = make_float2(v0, v1);
            }
}

// ---------------------------------------------------------------------------
// Flash attention, fp16 mma m16n8k16, no-max softmax via MUFU ex2 (log2e
// folded into the Q projection scale), P in registers.
// ---------------------------------------------------------------------------
#define KOFF(buf) ((buf) * 2 * TILE_W)
#define VOFF(buf) (KOFF(buf) + TILE_W)
#define ATTN_SMEM (4 * TILE_W * 4)    // 36864 bytes

__device__ __forceinline__ void stage_kv(uint32_t smb, int buf,
                                         const __half* __restrict__ Kg,
                                         const __half* __restrict__ VTg,
                                         int k0, int t)
{
    const uint32_t kb = smb + KOFF(buf) * 4;
    const uint32_t vb = smb + VOFF(buf) * 4;
#pragma unroll
    for (int i = 0; i < 4; i++) {
        const int chunk = t + i * 128;
        const int row = chunk >> 3, col = chunk & 7;
        CP16(kb + row * 144 + col * 16, Kg + (size_t)(k0 + row) * DK_ + col * 8);
        CP16(vb + row * 144 + col * 16, VTg + (size_t)row * S_ + k0 + col * 8);
    }
}

__global__ void __launch_bounds__(128, 2) attn_mma(const uint32_t* __restrict__ mbits,
                                                   __half* __restrict__ Y)
{
    extern __shared__ uint32_t smu[];
    const uint32_t smb = smem_u32(smu);

    const int h = blockIdx.x, qb = blockIdx.y, b = blockIdx.z;
    const int t = threadIdx.x;
    const int w = t >> 5, lane = t & 31;
    const int rr = lane >> 2, cc = lane & 3;

    const size_t base = (size_t)(h * B_ + b) * S_ * DK_;
    const __half* Qg  = g_q + base + (size_t)qb * 128 * DK_;
    const __half* Kg  = g_k + base;
    const __half* VTg = g_vT + base;

    const uint32_t* Qw = (const uint32_t*)Qg;
    uint32_t qf[4][2][4];
#pragma unroll
    for (int mf = 0; mf < 2; mf++) {
        const int q0 = w * 32 + mf * 16 + rr;
#pragma unroll
        for (int ks = 0; ks < 4; ks++) {
            qf[ks][mf][0] = Qw[q0 * 32 + ks * 8 + cc];
            qf[ks][mf][1] = Qw[(q0 + 8) * 32 + ks * 8 + cc];
            qf[ks][mf][2] = Qw[q0 * 32 + ks * 8 + cc + 4];
            qf[ks][mf][3] = Qw[(q0 + 8) * 32 + ks * 8 + cc + 4];
        }
    }

    float o0[8][4], o1[8][4];
#pragma unroll
    for (int i = 0; i < 8; i++)
#pragma unroll
        for (int j = 0; j < 4; j++) { o0[i][j] = 0.0f; o1[i][j] = 0.0f; }

    float l_[4] = {0.0f, 0.0f, 0.0f, 0.0f};
    const size_t mrow = ((size_t)b * S_ + (size_t)qb * 128 + w * 32 + rr) * (S_ / 32);

    stage_kv(smb, 0, Kg, VTg, 0, t);
    CP_COMMIT();

    for (int kb = 0; kb < NB; kb++) {
        const int buf = kb & 1;

        const uint2 M0 = *(const uint2*)&mbits[mrow + 0 * 8 * (S_ / 32) + kb * 2];
        const uint2 M1 = *(const uint2*)&mbits[mrow + 1 * 8 * (S_ / 32) + kb * 2];
        const uint2 M2 = *(const uint2*)&mbits[mrow + 2 * 8 * (S_ / 32) + kb * 2];
        const uint2 M3 = *(const uint2*)&mbits[mrow + 3 * 8 * (S_ / 32) + kb * 2];

        if (kb + 1 < NB) {
            stage_kv(smb, buf ^ 1, Kg, VTg, (kb + 1) * 64, t);
            CP_COMMIT();
            CP_WAIT(1);
        } else {
            CP_WAIT(0);
        }
        __syncthreads();

        const uint32_t* Ks = smu + KOFF(buf);
        const uint32_t* Vs = smu + VOFF(buf);

        uint32_t pf0[4][4], pf1[4][4];

#pragma unroll
        for (int half = 0; half < 2; half++) {
            float s0[4][4], s1[4][4];
#pragma unroll
            for (int i = 0; i < 4; i++)
#pragma unroll
                for (int j = 0; j < 4; j++) { s0[i][j] = 0.0f; s1[i][j] = 0.0f; }

#pragma unroll
            for (int ks = 0; ks < 4; ks++) {
#pragma unroll
                for (int nt = 0; nt < 4; nt++) {
                    const int n8 = (half * 4 + nt) * 8;
                    uint32_t bv[2];
                    bv[0] = Ks[(n8 + rr) * KW + ks * 8 + cc];
                    bv[1] = Ks[(n8 + rr) * KW + ks * 8 + cc + 4];
                    mma16(s0[nt], qf[ks][0], bv);
                    mma16(s1[nt], qf[ks][1], bv);
                }
            }

            // 2^s via MUFU + mask-zero + accumulate l + pack A-frags
#pragma unroll
            for (int nt = 0; nt < 4; nt++) {
                const int ntg = half * 4 + nt;
                const int sh = (ntg * 8 + 2 * cc) & 31;
                const uint32_t w0 = (ntg < 4) ? M0.x : M0.y;
                const uint32_t w1 = (ntg < 4) ? M1.x : M1.y;
                const uint32_t w2 = (ntg < 4) ? M2.x : M2.y;
                const uint32_t w3 = (ntg < 4) ? M3.x : M3.y;
                float e00 = ((w0 >> sh) & 1u)       ? 0.0f : ex2(s0[nt][0]);
                float e01 = ((w0 >> (sh + 1)) & 1u) ? 0.0f : ex2(s0[nt][1]);
                float e10 = ((w1 >> sh) & 1u)       ? 0.0f : ex2(s0[nt][2]);
                float e11 = ((w1 >> (sh + 1)) & 1u) ? 0.0f : ex2(s0[nt][3]);
                float e20 = ((w2 >> sh) & 1u)       ? 0.0f : ex2(s1[nt][0]);
                float e21 = ((w2 >> (sh + 1)) & 1u) ? 0.0f : ex2(s1[nt][1]);
                float e30 = ((w3 >> sh) & 1u)       ? 0.0f : ex2(s1[nt][2]);
                float e31 = ((w3 >> (sh + 1)) & 1u) ? 0.0f : ex2(s1[nt][3]);
                l_[0] += e00 + e01; l_[1] += e10 + e11;
                l_[2] += e20 + e21; l_[3] += e30 + e31;
                const int ks = ntg >> 1, hi = (ntg & 1) << 1;
                pf0[ks][hi + 0] = packh2(e00, e01);
                pf0[ks][hi + 1] = packh2(e10, e11);
                pf1[ks][hi + 0] = packh2(e20, e21);
                pf1[ks][hi + 1] = packh2(e30, e31);
            }
        }

#pragma unroll
        for (int ks = 0; ks < 4; ks++) {
#pragma unroll
            for (int nt = 0; nt < 8; nt++) {
                uint32_t bv[2];
                bv[0] = Vs[(nt * 8 + rr) * KW + ks * 8 + cc];
                bv[1] = Vs[(nt * 8 + rr) * KW + ks * 8 + cc + 4];
                mma16(o0[nt], pf0[ks], bv);
                mma16(o1[nt], pf1[ks], bv);
            }
        }
        __syncthreads();
    }

#pragma unroll
    for (int i = 0; i < 4; i++) {
        l_[i] += __shfl_xor_sync(0xffffffffu, l_[i], 1);
        l_[i] += __shfl_xor_sync(0xffffffffu, l_[i], 2);
    }
    const float il0 = 1.0f / l_[0], il1 = 1.0f / l_[1];
    const float il2 = 1.0f / l_[2], il3 = 1.0f / l_[3];

    const size_t yr0 = ((size_t)b * S_ + (size_t)qb * 128 + w * 32 + rr) * HD_ + h * DK_;
#pragma unroll
    for (int nt = 0; nt < 8; nt++) {
        const int col = nt * 8 + 2 * cc;
        *(__half2*)&Y[yr0 + col]                    = __floats2half2_rn(o0[nt][0] * il0, o0[nt][1] * il0);
        *(__half2*)&Y[yr0 + (size_t)8 * HD_ + col]  = __floats2half2_rn(o0[nt][2] * il1, o0[nt][3] * il1);
        *(__half2*)&Y[yr0 + (size_t)16 * HD_ + col] = __floats2half2_rn(o1[nt][0] * il2, o1[nt][3 - 2] * il2);
        *(__half2*)&Y[yr0 + (size_t)24 * HD_ + col] = __floats2half2_rn(o1[nt][2] * il3, o1[nt][3] * il3);
    }
}

// ---------------------------------------------------------------------------
extern "C" void kernel_launch(void* const* d_in, const int* in_sizes, int n_in,
                              void* d_out, int out_size)
{
    const float* q    = (const float*)d_in[0];
    const float* k    = (const float*)d_in[1];
    const float* v    = (const float*)d_in[2];
    const float* mask = (const float*)d_in[3];
    const float* Wq   = (const float*)d_in[4];
    const float* bq   = (const float*)d_in[5];
    const float* Wo   = (const float*)d_in[6];
    const float* bo   = (const float*)d_in[7];
    float* out = (float*)d_out;

    __half *gq, *gk, *gvT, *gy, *gWqT, *gWoT;
    uint32_t* gmb;
    cudaGetSymbolAddress((void**)&gq, g_q);
    cudaGetSymbolAddress((void**)&gk, g_k);
    cudaGetSymbolAddress((void**)&gvT, g_vT);
    cudaGetSymbolAddress((void**)&gy, g_y);
    cudaGetSymbolAddress((void**)&gWqT, g_WqT);
    cudaGetSymbolAddress((void**)&gWoT, g_WoT);
    cudaGetSymbolAddress((void**)&gmb, g_mb);

    cudaFuncSetAttribute(gemm_out_h, cudaFuncAttributeMaxDynamicSharedMemorySize,
                         GOUT_SMEM);

    const int Mrows = B_ * S_;   // 16384
    dim3 blk(128);

    // pre-passes
    pack_mask<<<(int)(((size_t)B_ * S_ * S_) / 256), 256>>>(mask, gmb);
    wT_kernel<<<dim3(HD_ / 32, DK_ / 32), 256>>>(Wq, gWqT, DK_, HD_);
    wT_kernel<<<dim3(DM_ / 32, HD_ / 32), 256>>>(Wo, gWoT, HD_, DM_);

    // fused projections (reference bug: Wq/bq for q, k AND v);
    // q epilogue scale = log2(e)/sqrt(DK) so attention uses ex2 directly
    dim3 gproj(HD_ / 64, Mrows / 64, 3);
    proj_h<<<gproj, blk, PROJ_SMEM>>>(q, k, v, gWqT, bq, gq, gk, gvT);

    // flash attention (fp16 mma): grid.x = heads so heads share mask bits in L2
    dim3 gattn(H_, S_ / 128, B_);
    attn_mma<<<gattn, blk, ATTN_SMEM>>>(gmb, gy);

    // output projection (fp16 in, fp32 out), 128x128 tiles
    dim3 gout(DM_ / 128, Mrows / 128);
    gemm_out_h<<<gout, 256, GOUT_SMEM>>>(gy, gWoT, bo, out);
}

// round 14
// speedup vs baseline: 1.3444x; 1.1013x over previous
#include <cuda_runtime.h>
#include <cuda_fp16.h>
#include <math.h>
#include <stdint.h>

#define B_  8
#define S_  2048
#define H_  8
#define DK_ 64
#define HD_ 512   // H_*DK_
#define DM_ 512
#define NB  (S_ / 64)   // kv blocks

// Scratch (static device arrays; allocation APIs are forbidden)
__device__ __align__(128) __half g_q[(size_t)H_ * B_ * S_ * DK_];
__device__ __align__(128) __half g_k[(size_t)H_ * B_ * S_ * DK_];
__device__ __align__(128) __half g_vT[(size_t)H_ * B_ * DK_ * S_];  // [h,b][d][s]
__device__ __align__(128) __half g_y[(size_t)B_ * S_ * HD_];        // attn out, fp16
__device__ __align__(128) __half g_WqT[HD_ * DK_];                  // [N=512][K=64]
__device__ __align__(128) __half g_WoT[DM_ * HD_];                  // [N=512][K=512]
__device__ uint32_t g_mb[(size_t)B_ * S_ * (S_ / 32)];   // bit-packed mask (4MB)

// ---------------------------------------------------------------------------
// helpers
// ---------------------------------------------------------------------------
// fp16: D += A(m16k16, row) * B(k16n8, col), fp32 accum
__device__ __forceinline__ void mma16(float* c, const uint32_t* a, const uint32_t* b) {
    asm volatile(
        "mma.sync.aligned.m16n8k16.row.col.f32.f16.f16.f32 "
        "{%0,%1,%2,%3}, {%4,%5,%6,%7}, {%8,%9}, {%0,%1,%2,%3};"
        : "+f"(c[0]), "+f"(c[1]), "+f"(c[2]), "+f"(c[3])
        : "r"(a[0]), "r"(a[1]), "r"(a[2]), "r"(a[3]), "r"(b[0]), "r"(b[1]));
}

// hardware MUFU.EX2 — 2^x (log2e is pre-folded into the Q scale)
__device__ __forceinline__ float ex2(float x) {
    float r;
    asm("ex2.approx.ftz.f32 %0, %1;" : "=f"(r) : "f"(x));
    return r;
}

__device__ __forceinline__ uint32_t smem_u32(const void* p) {
    uint32_t a;
    asm("{ .reg .u64 t; cvta.to.shared.u64 t, %1; cvt.u32.u64 %0, t; }"
        : "=r"(a) : "l"(p));
    return a;
}

__device__ __forceinline__ uint32_t packh2(float a, float b) {
    __half2 h = __floats2half2_rn(a, b);
    return *(uint32_t*)&h;
}

#define CP16(dst, src) \
    asm volatile("cp.async.cg.shared.global [%0], [%1], 16;" \
                 :: "r"(dst), "l"(src) : "memory")
#define CP_COMMIT() asm volatile("cp.async.commit_group;" ::: "memory")
#define CP_WAIT(n)  asm volatile("cp.async.wait_group %0;" :: "n"(n) : "memory")

// ---------------------------------------------------------------------------
// Weight transpose+convert: WT[n][k] = (half)W[k][n], coalesced
// ---------------------------------------------------------------------------
__global__ void wT_kernel(const float* __restrict__ W, __half* __restrict__ WT,
                          int K, int N)
{
    __shared__ float tile[32][33];
    const int n0 = blockIdx.x * 32, k0 = blockIdx.y * 32;
    const int tx = threadIdx.x & 31, ty = threadIdx.x >> 5;   // 256 threads
#pragma unroll
    for (int i = 0; i < 32; i += 8)
        tile[ty + i][tx] = W[(size_t)(k0 + ty + i) * N + n0 + tx];
    __syncthreads();
#pragma unroll
    for (int i = 0; i < 32; i += 8)
        WT[(size_t)(n0 + ty + i) * K + k0 + tx] = __float2half_rn(tile[tx][ty + i]);
}

// ---------------------------------------------------------------------------
// smem layout constants (stride 72 halves = 36 words, ==4 mod 32: conflict-free)
// ---------------------------------------------------------------------------
#define KW 36
#define TILE_W (64 * KW)              // 2304 words per 64-row tile

// ---------------------------------------------------------------------------
// MEGA kernel: grid (2, 128, 4), 256 threads.
//   z=0: q -> g_q   (128x256 proj tile, scale log2e/8, [h,b,s,d])
//   z=1: k -> g_k
//   z=2: v -> g_vT  (smem transpose, coalesced [h,b,d,s])
//   z=3: bit-pack the fp32 mask (DRAM-bound; overlaps the proj compute)
// ---------------------------------------------------------------------------
#define PA_W (128 * KW)               // A tile words: 4608
#define PW_W (256 * KW)               // W tile words: 9216
#define PROJ_SMEM ((PA_W + PW_W) * 4) // 55296 bytes

__global__ void __launch_bounds__(256) proj_mega(
    const float* __restrict__ q, const float* __restrict__ k,
    const float* __restrict__ v, const float* __restrict__ mask,
    const __half* __restrict__ WqT, const float* __restrict__ bias,
    __half* __restrict__ gq, __half* __restrict__ gk, __half* __restrict__ gvT,
    uint32_t* __restrict__ mb)
{
    extern __shared__ uint32_t smu[];
    const int t = threadIdx.x;
    const int w = t >> 5, lane = t & 31;
    const int z = blockIdx.z;

    // ---------------- z == 3 : mask bit-pack ----------------
    if (z == 3) {
        const int cta = blockIdx.y * 2 + blockIdx.x;           // 0..255
        const size_t base0 = (size_t)cta * 131072;             // floats per CTA
#pragma unroll 4
        for (int it = 0; it < 128; it++) {
            const size_t base = base0 + (size_t)(it * 8 + w) * 128;
            uint32_t bb[4];
#pragma unroll
            for (int j = 0; j < 4; j++) {
                const float f = mask[base + j * 32 + lane];
                bb[j] = __ballot_sync(0xffffffffu, f == 1.0f);
            }
            if (lane == 0)
                *(uint4*)&mb[base >> 5] = make_uint4(bb[0], bb[1], bb[2], bb[3]);
        }
        return;
    }

    // ---------------- z < 3 : projection, 128 rows x 256 cols ----------------
    const uint32_t smb = smem_u32(smu);
    const float* A = (z == 0) ? q : (z == 1) ? k : v;
    // q gets 1/sqrt(DK) * log2(e) so attention can use ex2 directly
    const float scale = (z == 0) ? 0.18033688011112042f : 1.0f;

    const int wm = w >> 1, wn = w & 1;          // warp grid 4m x 2n
    const int rr = lane >> 2, cc = lane & 3;
    const int row0 = blockIdx.y * 128, col0 = blockIdx.x * 256;

    // stage W tile (fp16, cp.async): rows = output cols col0..col0+255
#pragma unroll
    for (int i = 0; i < 8; i++) {
        const int chunk = t + i * 256;          // 0..2047
        const int row = chunk >> 3, col = chunk & 7;
        CP16(smb + PA_W * 4 + row * 144 + col * 16,
             WqT + (size_t)(col0 + row) * DK_ + col * 8);
    }
    CP_COMMIT();
    // stage A tile (fp32 -> fp16 in registers)
    {
        const float* Asrc = A + (size_t)row0 * DK_;
#pragma unroll
        for (int i = 0; i < 4; i++) {
            const int chunk = t + i * 256;      // 0..1023
            const int row = chunk >> 3, col = chunk & 7;
            const float4 f0 = *(const float4*)&Asrc[row * DK_ + col * 8];
            const float4 f1 = *(const float4*)&Asrc[row * DK_ + col * 8 + 4];
            uint4 u = make_uint4(packh2(f0.x, f0.y), packh2(f0.z, f0.w),
                                 packh2(f1.x, f1.y), packh2(f1.z, f1.w));
            *(uint4*)((char*)smu + row * 144 + col * 16) = u;
        }
    }
    CP_WAIT(0);
    __syncthreads();

    float o[2][16][4];
#pragma unroll
    for (int i = 0; i < 2; i++)
#pragma unroll
        for (int j = 0; j < 16; j++)
#pragma unroll
            for (int l = 0; l < 4; l++) o[i][j][l] = 0.0f;

    const uint32_t* Aw = smu;
    const uint32_t* Ww = smu + PA_W;
#pragma unroll
    for (int ks = 0; ks < 4; ks++) {
        uint32_t af[2][4];
#pragma unroll
        for (int mf = 0; mf < 2; mf++) {
            const int ar = (wm * 32 + mf * 16 + rr) * KW + ks * 8 + cc;
            af[mf][0] = Aw[ar];
            af[mf][1] = Aw[ar + 8 * KW];
            af[mf][2] = Aw[ar + 4];
            af[mf][3] = Aw[ar + 8 * KW + 4];
        }
#pragma unroll
        for (int nt = 0; nt < 16; nt++) {
            uint32_t bv[2];
            const int br = (wn * 128 + nt * 8 + rr) * KW + ks * 8 + cc;
            bv[0] = Ww[br];
            bv[1] = Ww[br + 4];
            mma16(o[0][nt], af[0], bv);
            mma16(o[1][nt], af[1], bv);
        }
    }

    const int bb = row0 >> 11;          // /S_ (tile within one b)
    const int s0 = row0 & (S_ - 1);

    if (z < 2) {
        __half* C = (z == 0) ? gq : gk;
#pragma unroll
        for (int mf = 0; mf < 2; mf++)
#pragma unroll
            for (int nt = 0; nt < 16; nt++)
#pragma unroll
                for (int half = 0; half < 2; half++) {
                    const int row = row0 + wm * 32 + mf * 16 + rr + half * 8;
                    const int col = col0 + wn * 128 + nt * 8 + 2 * cc;
                    const float v0 = (o[mf][nt][half * 2 + 0] + bias[col]) * scale;
                    const float v1 = (o[mf][nt][half * 2 + 1] + bias[col + 1]) * scale;
                    const int s = row & (S_ - 1);
                    const int hh = col >> 6, d = col & (DK_ - 1);
                    __half2 hv = __floats2half2_rn(v0, v1);
                    *(__half2*)&C[((size_t)(hh * B_ + bb) * S_ + s) * DK_ + d] = hv;
                }
    } else {
        // V: transpose through smem per 128-col phase, coalesced 16B rows out
        __half* Ts = (__half*)smu;       // [128 d][136 pad] halves = 34816 B
#pragma unroll
        for (int ph = 0; ph < 2; ph++) {
            __syncthreads();             // smem free (mma reads / prev phase done)
            if (wn == ph) {
#pragma unroll
                for (int mf = 0; mf < 2; mf++)
#pragma unroll
                    for (int nt = 0; nt < 16; nt++)
#pragma unroll
                        for (int half = 0; half < 2; half++) {
                            const int rloc = wm * 32 + mf * 16 + rr + half * 8;
                            const int cloc = nt * 8 + 2 * cc;
                            const int col = col0 + ph * 128 + cloc;
                            const float v0 = o[mf][nt][half * 2 + 0] + bias[col];
                            const float v1 = o[mf][nt][half * 2 + 1] + bias[col + 1];
                            Ts[cloc * 136 + rloc]       = __float2half_rn(v0);
                            Ts[(cloc + 1) * 136 + rloc] = __float2half_rn(v1);
                        }
            }
            __syncthreads();
#pragma unroll
            for (int i = 0; i < 8; i++) {
                const int j = t + i * 256;               // 0..2047
                const int dl = j >> 4, sc = (j & 15) * 8;
                const int col = col0 + ph * 128 + dl;
                const int hh = col >> 6, d = col & (DK_ - 1);
                uint4 val = *(uint4*)&Ts[dl * 136 + sc];
                *(uint4*)&gvT[((size_t)(hh * B_ + bb) * DK_ + d) * S_ + s0 + sc] = val;
            }
        }
    }
}

// ---------------------------------------------------------------------------
// Output GEMM, fp16 in / fp32 out: 128x128 CTA tile, 256 threads, 8 warps
// (2m x 4n), K=512 double-buffered. Warp tile 64x32.
// ---------------------------------------------------------------------------
#define OT_W (128 * KW)               // words per 128-row tile: 4608
#define GOUT_SMEM (4 * OT_W * 4)      // 73728 bytes

__device__ __forceinline__ void stage_h256(uint32_t dst, const __half* __restrict__ src,
                                           int stride_h, int t)
{
#pragma unroll
    for (int i = 0; i < 4; i++) {
        const int chunk = t + i * 256;          // 0..1023 (256 threads, 128 rows)
        const int row = chunk >> 3, col = chunk & 7;
        CP16(dst + row * 144 + col * 16, src + (size_t)row * stride_h + col * 8);
    }
}

__global__ void __launch_bounds__(256) gemm_out_h(
    const __half* __restrict__ A, const __half* __restrict__ WT,
    const float* __restrict__ bias, float* __restrict__ C)
{
    extern __shared__ uint32_t smu[];
    const uint32_t smb = smem_u32(smu);

    const int t = threadIdx.x;
    const int w = t >> 5, lane = t & 31;
    const int wm = w >> 2, wn = w & 3;          // warp grid 2m x 4n
    const int rr = lane >> 2, cc = lane & 3;
    const int row0 = blockIdx.y * 128, col0 = blockIdx.x * 128;
    const int K = HD_, N = DM_;

    float o[4][4][4];                            // [mf][nt][frag]
#pragma unroll
    for (int i = 0; i < 4; i++)
#pragma unroll
        for (int j = 0; j < 4; j++)
#pragma unroll
            for (int l = 0; l < 4; l++) o[i][j][l] = 0.0f;

    stage_h256(smb, A + (size_t)row0 * K, K, t);
    stage_h256(smb + OT_W * 4, WT + (size_t)col0 * K, K, t);
    CP_COMMIT();

    for (int kb = 0; kb < K / 64; kb++) {
        const int buf = kb & 1;
        if (kb + 1 < K / 64) {
            const uint32_t nb = smb + (buf ^ 1) * 2 * OT_W * 4;
            stage_h256(nb, A + (size_t)row0 * K + (kb + 1) * 64, K, t);
            stage_h256(nb + OT_W * 4, WT + (size_t)col0 * K + (kb + 1) * 64, K, t);
            CP_COMMIT();
            CP_WAIT(1);
        } else {
            CP_WAIT(0);
        }
        __syncthreads();

        const uint32_t* Aw = smu + buf * 2 * OT_W;
        const uint32_t* Bw = Aw + OT_W;
#pragma unroll
        for (int ks = 0; ks < 4; ks++) {
            uint32_t af[4][4];
#pragma unroll
            for (int mf = 0; mf < 4; mf++) {
                const int ar = (wm * 64 + mf * 16 + rr) * KW + ks * 8 + cc;
                af[mf][0] = Aw[ar];
                af[mf][1] = Aw[ar + 8 * KW];
                af[mf][2] = Aw[ar + 4];
                af[mf][3] = Aw[ar + 8 * KW + 4];
            }
#pragma unroll
            for (int nt = 0; nt < 4; nt++) {
                uint32_t bv[2];
                const int br = (wn * 32 + nt * 8 + rr) * KW + ks * 8 + cc;
                bv[0] = Bw[br];
                bv[1] = Bw[br + 4];
#pragma unroll
                for (int mf = 0; mf < 4; mf++)
                    mma16(o[mf][nt], af[mf], bv);
            }
        }
        __syncthreads();
    }

#pragma unroll
    for (int mf = 0; mf < 4; mf++)
#pragma unroll
        for (int nt = 0; nt < 4; nt++)
#pragma unroll
            for (int half = 0; half < 2; half++) {
                const int row = row0 + wm * 64 + mf * 16 + rr + half * 8;
                const int col = col0 + wn * 32 + nt * 8 + 2 * cc;
                const float v0 = o[mf][nt][half * 2 + 0] + bias[col];
                const float v1 = o[mf][nt][half * 2 + 1] + bias[col + 1];
                *(float2*)&C[(size_t)row * N + col] = make_float2(v0, v1);
            }
}

// ---------------------------------------------------------------------------
// Flash attention, fp16 mma m16n8k16, no-max softmax via MUFU ex2 (log2e
// folded into the Q projection scale), P in registers.
// ---------------------------------------------------------------------------
#define KOFF(buf) ((buf) * 2 * TILE_W)
#define VOFF(buf) (KOFF(buf) + TILE_W)
#define ATTN_SMEM (4 * TILE_W * 4)    // 36864 bytes

__device__ __forceinline__ void stage_kv(uint32_t smb, int buf,
                                         const __half* __restrict__ Kg,
                                         const __half* __restrict__ VTg,
                                         int k0, int t)
{
    const uint32_t kb = smb + KOFF(buf) * 4;
    const uint32_t vb = smb + VOFF(buf) * 4;
#pragma unroll
    for (int i = 0; i < 4; i++) {
        const int chunk = t + i * 128;
        const int row = chunk >> 3, col = chunk & 7;
        CP16(kb + row * 144 + col * 16, Kg + (size_t)(k0 + row) * DK_ + col * 8);
        CP16(vb + row * 144 + col * 16, VTg + (size_t)row * S_ + k0 + col * 8);
    }
}

__global__ void __launch_bounds__(128, 2) attn_mma(const uint32_t* __restrict__ mbits,
                                                   __half* __restrict__ Y)
{
    extern __shared__ uint32_t smu[];
    const uint32_t smb = smem_u32(smu);

    const int h = blockIdx.x, qb = blockIdx.y, b = blockIdx.z;
    const int t = threadIdx.x;
    const int w = t >> 5, lane = t & 31;
    const int rr = lane >> 2, cc = lane & 3;

    const size_t base = (size_t)(h * B_ + b) * S_ * DK_;
    const __half* Qg  = g_q + base + (size_t)qb * 128 * DK_;
    const __half* Kg  = g_k + base;
    const __half* VTg = g_vT + base;

    const uint32_t* Qw = (const uint32_t*)Qg;
    uint32_t qf[4][2][4];
#pragma unroll
    for (int mf = 0; mf < 2; mf++) {
        const int q0 = w * 32 + mf * 16 + rr;
#pragma unroll
        for (int ks = 0; ks < 4; ks++) {
            qf[ks][mf][0] = Qw[q0 * 32 + ks * 8 + cc];
            qf[ks][mf][1] = Qw[(q0 + 8) * 32 + ks * 8 + cc];
            qf[ks][mf][2] = Qw[q0 * 32 + ks * 8 + cc + 4];
            qf[ks][mf][3] = Qw[(q0 + 8) * 32 + ks * 8 + cc + 4];
        }
    }

    float o0[8][4], o1[8][4];
#pragma unroll
    for (int i = 0; i < 8; i++)
#pragma unroll
        for (int j = 0; j < 4; j++) { o0[i][j] = 0.0f; o1[i][j] = 0.0f; }

    float l_[4] = {0.0f, 0.0f, 0.0f, 0.0f};
    const size_t mrow = ((size_t)b * S_ + (size_t)qb * 128 + w * 32 + rr) * (S_ / 32);

    stage_kv(smb, 0, Kg, VTg, 0, t);
    CP_COMMIT();

    for (int kb = 0; kb < NB; kb++) {
        const int buf = kb & 1;

        const uint2 M0 = *(const uint2*)&mbits[mrow + 0 * 8 * (S_ / 32) + kb * 2];
        const uint2 M1 = *(const uint2*)&mbits[mrow + 1 * 8 * (S_ / 32) + kb * 2];
        const uint2 M2 = *(const uint2*)&mbits[mrow + 2 * 8 * (S_ / 32) + kb * 2];
        const uint2 M3 = *(const uint2*)&mbits[mrow + 3 * 8 * (S_ / 32) + kb * 2];

        if (kb + 1 < NB) {
            stage_kv(smb, buf ^ 1, Kg, VTg, (kb + 1) * 64, t);
            CP_COMMIT();
            CP_WAIT(1);
        } else {
            CP_WAIT(0);
        }
        __syncthreads();

        const uint32_t* Ks = smu + KOFF(buf);
        const uint32_t* Vs = smu + VOFF(buf);

        uint32_t pf0[4][4], pf1[4][4];

#pragma unroll
        for (int half = 0; half < 2; half++) {
            float s0[4][4], s1[4][4];
#pragma unroll
            for (int i = 0; i < 4; i++)
#pragma unroll
                for (int j = 0; j < 4; j++) { s0[i][j] = 0.0f; s1[i][j] = 0.0f; }

#pragma unroll
            for (int ks = 0; ks < 4; ks++) {
#pragma unroll
                for (int nt = 0; nt < 4; nt++) {
                    const int n8 = (half * 4 + nt) * 8;
                    uint32_t bv[2];
                    bv[0] = Ks[(n8 + rr) * KW + ks * 8 + cc];
                    bv[1] = Ks[(n8 + rr) * KW + ks * 8 + cc + 4];
                    mma16(s0[nt], qf[ks][0], bv);
                    mma16(s1[nt], qf[ks][1], bv);
                }
            }

            // 2^s via MUFU + mask-zero + accumulate l + pack A-frags
#pragma unroll
            for (int nt = 0; nt < 4; nt++) {
                const int ntg = half * 4 + nt;
                const int sh = (ntg * 8 + 2 * cc) & 31;
                const uint32_t w0 = (ntg < 4) ? M0.x : M0.y;
                const uint32_t w1 = (ntg < 4) ? M1.x : M1.y;
                const uint32_t w2 = (ntg < 4) ? M2.x : M2.y;
                const uint32_t w3 = (ntg < 4) ? M3.x : M3.y;
                float e00 = ((w0 >> sh) & 1u)       ? 0.0f : ex2(s0[nt][0]);
                float e01 = ((w0 >> (sh + 1)) & 1u) ? 0.0f : ex2(s0[nt][1]);
                float e10 = ((w1 >> sh) & 1u)       ? 0.0f : ex2(s0[nt][2]);
                float e11 = ((w1 >> (sh + 1)) & 1u) ? 0.0f : ex2(s0[nt][3]);
                float e20 = ((w2 >> sh) & 1u)       ? 0.0f : ex2(s1[nt][0]);
                float e21 = ((w2 >> (sh + 1)) & 1u) ? 0.0f : ex2(s1[nt][1]);
                float e30 = ((w3 >> sh) & 1u)       ? 0.0f : ex2(s1[nt][2]);
                float e31 = ((w3 >> (sh + 1)) & 1u) ? 0.0f : ex2(s1[nt][3]);
                l_[0] += e00 + e01; l_[1] += e10 + e11;
                l_[2] += e20 + e21; l_[3] += e30 + e31;
                const int ks = ntg >> 1, hi = (ntg & 1) << 1;
                pf0[ks][hi + 0] = packh2(e00, e01);
                pf0[ks][hi + 1] = packh2(e10, e11);
                pf1[ks][hi + 0] = packh2(e20, e21);
                pf1[ks][hi + 1] = packh2(e30, e31);
            }
        }

#pragma unroll
        for (int ks = 0; ks < 4; ks++) {
#pragma unroll
            for (int nt = 0; nt < 8; nt++) {
                uint32_t bv[2];
                bv[0] = Vs[(nt * 8 + rr) * KW + ks * 8 + cc];
                bv[1] = Vs[(nt * 8 + rr) * KW + ks * 8 + cc + 4];
                mma16(o0[nt], pf0[ks], bv);
                mma16(o1[nt], pf1[ks], bv);
            }
        }
        __syncthreads();
    }

#pragma unroll
    for (int i = 0; i < 4; i++) {
        l_[i] += __shfl_xor_sync(0xffffffffu, l_[i], 1);
        l_[i] += __shfl_xor_sync(0xffffffffu, l_[i], 2);
    }
    const float il0 = 1.0f / l_[0], il1 = 1.0f / l_[1];
    const float il2 = 1.0f / l_[2], il3 = 1.0f / l_[3];

    const size_t yr0 = ((size_t)b * S_ + (size_t)qb * 128 + w * 32 + rr) * HD_ + h * DK_;
#pragma unroll
    for (int nt = 0; nt < 8; nt++) {
        const int col = nt * 8 + 2 * cc;
        *(__half2*)&Y[yr0 + col]                    = __floats2half2_rn(o0[nt][0] * il0, o0[nt][1] * il0);
        *(__half2*)&Y[yr0 + (size_t)8 * HD_ + col]  = __floats2half2_rn(o0[nt][2] * il1, o0[nt][3] * il1);
        *(__half2*)&Y[yr0 + (size_t)16 * HD_ + col] = __floats2half2_rn(o1[nt][0] * il2, o1[nt][1] * il2);
        *(__half2*)&Y[yr0 + (size_t)24 * HD_ + col] = __floats2half2_rn(o1[nt][2] * il3, o1[nt][3] * il3);
    }
}

// ---------------------------------------------------------------------------
extern "C" void kernel_launch(void* const* d_in, const int* in_sizes, int n_in,
                              void* d_out, int out_size)
{
    const float* q    = (const float*)d_in[0];
    const float* k    = (const float*)d_in[1];
    const float* v    = (const float*)d_in[2];
    const float* mask = (const float*)d_in[3];
    const float* Wq   = (const float*)d_in[4];
    const float* bq   = (const float*)d_in[5];
    const float* Wo   = (const float*)d_in[6];
    const float* bo   = (const float*)d_in[7];
    float* out = (float*)d_out;

    __half *gq, *gk, *gvT, *gy, *gWqT, *gWoT;
    uint32_t* gmb;
    cudaGetSymbolAddress((void**)&gq, g_q);
    cudaGetSymbolAddress((void**)&gk, g_k);
    cudaGetSymbolAddress((void**)&gvT, g_vT);
    cudaGetSymbolAddress((void**)&gy, g_y);
    cudaGetSymbolAddress((void**)&gWqT, g_WqT);
    cudaGetSymbolAddress((void**)&gWoT, g_WoT);
    cudaGetSymbolAddress((void**)&gmb, g_mb);

    cudaFuncSetAttribute(gemm_out_h, cudaFuncAttributeMaxDynamicSharedMemorySize,
                         GOUT_SMEM);
    cudaFuncSetAttribute(proj_mega, cudaFuncAttributeMaxDynamicSharedMemorySize,
                         PROJ_SMEM);

    const int Mrows = B_ * S_;   // 16384

    // weight transpose+convert (proj_mega consumes WqT)
    wT_kernel<<<dim3(HD_ / 32, DK_ / 32), 256>>>(Wq, gWqT, DK_, HD_);
    wT_kernel<<<dim3(DM_ / 32, HD_ / 32), 256>>>(Wo, gWoT, HD_, DM_);

    // fused projections + mask pack (reference bug: Wq/bq for q, k AND v);
    // q epilogue scale = log2(e)/sqrt(DK) so attention uses ex2 directly.
    // z=3 CTAs bit-pack the mask, overlapping proj compute with mask DRAM.
    dim3 gproj(HD_ / 256, Mrows / 128, 4);
    proj_mega<<<gproj, 256, PROJ_SMEM>>>(q, k, v, mask, gWqT, bq,
                                         gq, gk, gvT, gmb);

    // flash attention (fp16 mma): grid.x = heads so heads share mask bits in L2
    dim3 gattn(H_, S_ / 128, B_);
    attn_mma<<<gattn, 128, ATTN_SMEM>>>(gmb, gy);

    // output projection (fp16 in, fp32 out), 128x128 tiles
    dim3 gout(DM_ / 128, Mrows / 128);
    gemm_out_h<<<gout, 256, GOUT_SMEM>>>(gy, gWoT, bo, out);
}